// round 3
// baseline (speedup 1.0000x reference)
#include <cuda_runtime.h>

#define N_NODES 50000
#define DIM     512
#define N_EDGES 1600000

// ---------------- scratch (static __device__, no allocation) ----------------
__device__ int   g_offsets[N_NODES + 1];        // CSR row offsets (by dst)
__device__ int   g_cursor [N_NODES];            // fill cursors
__device__ int   g_src_sorted[N_EDGES];         // src permuted by dst-bucket
__device__ float g_w_sorted  [N_EDGES];         // weight permuted by dst-bucket
__device__ float g_agg[N_NODES * DIM];          // segment_sum(x[src]*w) : [N, D]

// ---------------- kernel 1: zero offsets ----------------
__global__ void zero_offsets_kernel() {
    int i = blockIdx.x * blockDim.x + threadIdx.x;
    if (i <= N_NODES) g_offsets[i] = 0;
}

// ---------------- kernel 2: histogram of dst ----------------
__global__ void hist_kernel(const int* __restrict__ dst) {
    int e = blockIdx.x * blockDim.x + threadIdx.x;
    if (e < N_EDGES) atomicAdd(&g_offsets[dst[e] + 1], 1);
}

// ---------------- kernel 3: single-block exclusive scan over 50001 ----------------
__global__ void scan_kernel() {
    __shared__ int partials[1024];
    const int tid = threadIdx.x;
    const int CH  = (N_NODES + 1023) / 1024;   // 49
    int begin = tid * CH;
    int end   = begin + CH; if (end > N_NODES) end = N_NODES;

    int sum = 0;
    for (int i = begin; i < end; ++i) sum += g_offsets[i + 1];
    partials[tid] = sum;
    __syncthreads();
    // Hillis-Steele inclusive scan over 1024 partials
    for (int off = 1; off < 1024; off <<= 1) {
        int v = (tid >= off) ? partials[tid - off] : 0;
        __syncthreads();
        partials[tid] += v;
        __syncthreads();
    }
    int run = (tid > 0) ? partials[tid - 1] : 0;
    for (int i = begin; i < end; ++i) {
        int c = g_offsets[i + 1];
        g_cursor[i] = run;           // start offset of bucket i
        run += c;
        g_offsets[i + 1] = run;      // inclusive prefix -> offsets[i+1]
    }
    // g_offsets[0] is already 0 from zero_offsets_kernel
}

// ---------------- kernel 4: scatter edges into dst buckets ----------------
__global__ void fill_kernel(const int* __restrict__ src,
                            const int* __restrict__ dst,
                            const float* __restrict__ w) {
    int e = blockIdx.x * blockDim.x + threadIdx.x;
    if (e < N_EDGES) {
        int d   = dst[e];
        int pos = atomicAdd(&g_cursor[d], 1);
        g_src_sorted[pos] = src[e];
        g_w_sorted[pos]   = w[e];
    }
}

// ---------------- kernel 5: per-node gather aggregation ----------------
// one CTA (128 threads) per node; each thread owns one float4 (4 cols)
__global__ __launch_bounds__(128) void aggregate_kernel(const float4* __restrict__ x4) {
    const int n   = blockIdx.x;
    const int tid = threadIdx.x;     // 0..127, covers 512 cols as float4
    const int beg = g_offsets[n];
    const int end = g_offsets[n + 1];

    float4 acc0 = make_float4(0.f, 0.f, 0.f, 0.f);
    float4 acc1 = make_float4(0.f, 0.f, 0.f, 0.f);

    int e = beg;
    for (; e + 1 < end; e += 2) {
        int   s0 = g_src_sorted[e];
        int   s1 = g_src_sorted[e + 1];
        float w0 = g_w_sorted[e];
        float w1 = g_w_sorted[e + 1];
        float4 v0 = x4[s0 * 128 + tid];
        float4 v1 = x4[s1 * 128 + tid];
        acc0.x += w0 * v0.x;  acc0.y += w0 * v0.y;
        acc0.z += w0 * v0.z;  acc0.w += w0 * v0.w;
        acc1.x += w1 * v1.x;  acc1.y += w1 * v1.y;
        acc1.z += w1 * v1.z;  acc1.w += w1 * v1.w;
    }
    if (e < end) {
        int   s0 = g_src_sorted[e];
        float w0 = g_w_sorted[e];
        float4 v0 = x4[s0 * 128 + tid];
        acc0.x += w0 * v0.x;  acc0.y += w0 * v0.y;
        acc0.z += w0 * v0.z;  acc0.w += w0 * v0.w;
    }
    acc0.x += acc1.x; acc0.y += acc1.y; acc0.z += acc1.z; acc0.w += acc1.w;
    reinterpret_cast<float4*>(g_agg)[n * 128 + tid] = acc0;
}

// ---------------- kernel 6: SGEMM (agg @ W) + bias + relu + residual ----------------
// C[M,N] = A[M,K] * B[K,N];  out = relu(C + bias) + X
#define BM 128
#define BN 128
#define BK 16
#define TM 8
#define TN 8

__global__ __launch_bounds__(256) void gemm_epilogue_kernel(
    const float* __restrict__ A,    // g_agg [M, K]
    const float* __restrict__ B,    // W     [K, N]
    const float* __restrict__ bias, // [N]
    const float* __restrict__ X,    // [M, N]
    float* __restrict__ out)        // [M, N]
{
    const int M = N_NODES, N = DIM, K = DIM;

    __shared__ float As[BK][BM];    // transposed A tile
    __shared__ float Bs[BK][BN];

    const int bx  = blockIdx.x;     // N tile index (0..3)
    const int by  = blockIdx.y;     // M tile index (0..390)
    const int tid = threadIdx.x;    // 0..255
    const int tx  = tid & 15;       // 0..15 -> col group
    const int ty  = tid >> 4;       // 0..15 -> row group

    const int rowBase = by * BM;
    const int colBase = bx * BN;

    float acc[TM][TN];
    #pragma unroll
    for (int i = 0; i < TM; ++i)
        #pragma unroll
        for (int j = 0; j < TN; ++j) acc[i][j] = 0.f;

    for (int k0 = 0; k0 < K; k0 += BK) {
        // load A tile (128 rows x 16 cols) : 512 float4, 2 per thread
        #pragma unroll
        for (int p = 0; p < 2; ++p) {
            int f    = tid + p * 256;          // 0..511
            int row  = f >> 2;                 // 0..127
            int col4 = f & 3;                  // 0..3 (each = 4 floats)
            int grow = rowBase + row;
            float4 v = make_float4(0.f, 0.f, 0.f, 0.f);
            if (grow < M)
                v = *reinterpret_cast<const float4*>(&A[grow * K + k0 + col4 * 4]);
            As[col4 * 4 + 0][row] = v.x;
            As[col4 * 4 + 1][row] = v.y;
            As[col4 * 4 + 2][row] = v.z;
            As[col4 * 4 + 3][row] = v.w;
        }
        // load B tile (16 rows x 128 cols) : 512 float4, 2 per thread
        #pragma unroll
        for (int p = 0; p < 2; ++p) {
            int f    = tid + p * 256;
            int rowb = f >> 5;                 // 0..15
            int col4 = f & 31;                 // 0..31
            float4 v = *reinterpret_cast<const float4*>(
                &B[(k0 + rowb) * N + colBase + col4 * 4]);
            *reinterpret_cast<float4*>(&Bs[rowb][col4 * 4]) = v;
        }
        __syncthreads();

        #pragma unroll
        for (int kk = 0; kk < BK; ++kk) {
            float a[TM], bb[TN];
            #pragma unroll
            for (int i = 0; i < TM; ++i) a[i]  = As[kk][ty * TM + i];
            #pragma unroll
            for (int j = 0; j < TN; ++j) bb[j] = Bs[kk][tx * TN + j];
            #pragma unroll
            for (int i = 0; i < TM; ++i)
                #pragma unroll
                for (int j = 0; j < TN; ++j)
                    acc[i][j] += a[i] * bb[j];
        }
        __syncthreads();
    }

    // epilogue: out = relu(acc + bias) + X
    #pragma unroll
    for (int i = 0; i < TM; ++i) {
        int row = rowBase + ty * TM + i;
        if (row >= M) continue;
        #pragma unroll
        for (int j4 = 0; j4 < TN / 4; ++j4) {
            int col = colBase + tx * TN + j4 * 4;
            float4 xb = *reinterpret_cast<const float4*>(&bias[col]);
            float4 xr = *reinterpret_cast<const float4*>(&X[row * N + col]);
            float4 r;
            float c0 = acc[i][j4 * 4 + 0] + xb.x;
            float c1 = acc[i][j4 * 4 + 1] + xb.y;
            float c2 = acc[i][j4 * 4 + 2] + xb.z;
            float c3 = acc[i][j4 * 4 + 3] + xb.w;
            r.x = fmaxf(c0, 0.f) + xr.x;
            r.y = fmaxf(c1, 0.f) + xr.y;
            r.z = fmaxf(c2, 0.f) + xr.z;
            r.w = fmaxf(c3, 0.f) + xr.w;
            *reinterpret_cast<float4*>(&out[row * N + col]) = r;
        }
    }
}

// ---------------- launch ----------------
extern "C" void kernel_launch(void* const* d_in, const int* in_sizes, int n_in,
                              void* d_out, int out_size) {
    const float* x    = (const float*)d_in[0];  // [N, D]
    const float* W    = (const float*)d_in[1];  // [D, D]
    const float* b    = (const float*)d_in[2];  // [D]
    const float* ew   = (const float*)d_in[3];  // [E]
    const int*   esrc = (const int*)  d_in[4];  // [E]
    const int*   edst = (const int*)  d_in[5];  // [E]
    float* out = (float*)d_out;

    // device-global scratch addresses
    float* agg_ptr;
    cudaGetSymbolAddress((void**)&agg_ptr, g_agg);

    zero_offsets_kernel<<<(N_NODES + 256) / 256, 256>>>();
    hist_kernel<<<N_EDGES / 256, 256>>>(edst);
    scan_kernel<<<1, 1024>>>();
    fill_kernel<<<N_EDGES / 256, 256>>>(esrc, edst, ew);
    aggregate_kernel<<<N_NODES, 128>>>(reinterpret_cast<const float4*>(x));

    dim3 ggrid(DIM / BN, (N_NODES + BM - 1) / BM);
    gemm_epilogue_kernel<<<ggrid, 256>>>(agg_ptr, W, b, x, out);
}

// round 8
// speedup vs baseline: 2.5705x; 2.5705x over previous
#include <cuda_runtime.h>
#include <cstdint>

#define N_NODES 50000
#define DIM     512
#define N_EDGES 1600000

// ---------------- scratch (static __device__, no allocation) ----------------
__device__ int   g_offsets[N_NODES + 1];
__device__ int   g_cursor [N_NODES];
__device__ int   g_src_sorted[N_EDGES];
__device__ float g_w_sorted  [N_EDGES];
__device__ float g_agg[N_NODES * DIM];   // tf32-rounded aggregation result [M, K]
__device__ float g_Wr [DIM * DIM];       // tf32-rounded W [K, N] (same layout)

// ---------------- helpers ----------------
__device__ __forceinline__ uint32_t smem_u32(const void* p) {
    uint32_t a;
    asm("{ .reg .u64 t; cvta.to.shared.u64 t, %1; cvt.u32.u64 %0, t; }" : "=r"(a) : "l"(p));
    return a;
}
__device__ __forceinline__ uint32_t f2tf32(float f) {
    uint32_t u;
    asm("cvt.rna.tf32.f32 %0, %1;" : "=r"(u) : "f"(f));
    return u;
}
__device__ __forceinline__ void cp16(uint32_t dst, const void* src, uint32_t bytes) {
    asm volatile("cp.async.ca.shared.global [%0], [%1], 16, %2;"
                 :: "r"(dst), "l"(src), "r"(bytes) : "memory");
}
#define CP_COMMIT() asm volatile("cp.async.commit_group;" ::: "memory")
#define CP_WAIT_1() asm volatile("cp.async.wait_group 1;" ::: "memory")
#define CP_WAIT_0() asm volatile("cp.async.wait_group 0;" ::: "memory")

__device__ __forceinline__ void mma_tf32(float* c, const uint32_t* a, const uint32_t* b) {
    asm volatile(
        "mma.sync.aligned.m16n8k8.row.col.f32.tf32.tf32.f32 "
        "{%0,%1,%2,%3}, {%4,%5,%6,%7}, {%8,%9}, {%0,%1,%2,%3};"
        : "+f"(c[0]), "+f"(c[1]), "+f"(c[2]), "+f"(c[3])
        : "r"(a[0]), "r"(a[1]), "r"(a[2]), "r"(a[3]), "r"(b[0]), "r"(b[1]));
}

// ---------------- kernel 1: zero offsets ----------------
__global__ void zero_offsets_kernel() {
    int i = blockIdx.x * blockDim.x + threadIdx.x;
    if (i <= N_NODES) g_offsets[i] = 0;
}

// ---------------- kernel 2: histogram of dst ----------------
__global__ void hist_kernel(const int* __restrict__ dst) {
    int e = blockIdx.x * blockDim.x + threadIdx.x;
    if (e < N_EDGES) atomicAdd(&g_offsets[dst[e] + 1], 1);
}

// ---------------- kernel 3: single-block exclusive scan ----------------
__global__ void scan_kernel() {
    __shared__ int partials[1024];
    const int tid = threadIdx.x;
    const int CH  = (N_NODES + 1023) / 1024;
    int begin = tid * CH;
    int end   = begin + CH; if (end > N_NODES) end = N_NODES;

    int sum = 0;
    for (int i = begin; i < end; ++i) sum += g_offsets[i + 1];
    partials[tid] = sum;
    __syncthreads();
    for (int off = 1; off < 1024; off <<= 1) {
        int v = (tid >= off) ? partials[tid - off] : 0;
        __syncthreads();
        partials[tid] += v;
        __syncthreads();
    }
    int run = (tid > 0) ? partials[tid - 1] : 0;
    for (int i = begin; i < end; ++i) {
        int c = g_offsets[i + 1];
        g_cursor[i] = run;
        run += c;
        g_offsets[i + 1] = run;
    }
}

// ---------------- kernel 4: scatter edges into dst buckets ----------------
__global__ void fill_kernel(const int* __restrict__ src,
                            const int* __restrict__ dst,
                            const float* __restrict__ w) {
    int e = blockIdx.x * blockDim.x + threadIdx.x;
    if (e < N_EDGES) {
        int d   = dst[e];
        int pos = atomicAdd(&g_cursor[d], 1);
        g_src_sorted[pos] = src[e];
        g_w_sorted[pos]   = w[e];
    }
}

// ---------------- kernel 5: gather aggregation (+ tf32 round on store) ----------------
__global__ __launch_bounds__(128) void aggregate_kernel(const float4* __restrict__ x4) {
    const int n   = blockIdx.x;
    const int tid = threadIdx.x;
    const int beg = g_offsets[n];
    const int end = g_offsets[n + 1];

    float4 acc0 = make_float4(0.f, 0.f, 0.f, 0.f);
    float4 acc1 = make_float4(0.f, 0.f, 0.f, 0.f);

    int e = beg;
    for (; e + 1 < end; e += 2) {
        int   s0 = g_src_sorted[e];
        int   s1 = g_src_sorted[e + 1];
        float w0 = g_w_sorted[e];
        float w1 = g_w_sorted[e + 1];
        float4 v0 = x4[s0 * 128 + tid];
        float4 v1 = x4[s1 * 128 + tid];
        acc0.x += w0 * v0.x;  acc0.y += w0 * v0.y;
        acc0.z += w0 * v0.z;  acc0.w += w0 * v0.w;
        acc1.x += w1 * v1.x;  acc1.y += w1 * v1.y;
        acc1.z += w1 * v1.z;  acc1.w += w1 * v1.w;
    }
    if (e < end) {
        int   s0 = g_src_sorted[e];
        float w0 = g_w_sorted[e];
        float4 v0 = x4[s0 * 128 + tid];
        acc0.x += w0 * v0.x;  acc0.y += w0 * v0.y;
        acc0.z += w0 * v0.z;  acc0.w += w0 * v0.w;
    }
    acc0.x += acc1.x; acc0.y += acc1.y; acc0.z += acc1.z; acc0.w += acc1.w;
    float4 r;
    r.x = __uint_as_float(f2tf32(acc0.x));
    r.y = __uint_as_float(f2tf32(acc0.y));
    r.z = __uint_as_float(f2tf32(acc0.z));
    r.w = __uint_as_float(f2tf32(acc0.w));
    reinterpret_cast<float4*>(g_agg)[n * 128 + tid] = r;
}

// ---------------- kernel 6: round W to tf32 (elementwise, layout preserved) ----------------
__global__ __launch_bounds__(256) void round_w_kernel(const float4* __restrict__ W4) {
    int i = blockIdx.x * blockDim.x + threadIdx.x;   // over DIM*DIM/4
    float4 v = W4[i];
    float4 r;
    r.x = __uint_as_float(f2tf32(v.x));
    r.y = __uint_as_float(f2tf32(v.y));
    r.z = __uint_as_float(f2tf32(v.z));
    r.w = __uint_as_float(f2tf32(v.w));
    reinterpret_cast<float4*>(g_Wr)[i] = r;
}

// ---------------- kernel 7: tf32 mma.sync GEMM + fused epilogue ----------------
// C[M,N] = A[M,K] @ B[K,N];  out = relu(C + bias) + X
// BM=128 BN=128 BK=32; 256 threads = 8 warps (4 M x 2 N), warp tile 32x64.
#define BM 128
#define BN 128
#define BK 32
#define NKI (DIM / BK)          // 16 k-iterations
#define AS_STRIDE 36            // 32 floats + pad (bank-conflict-free frags)
#define BS_STRIDE 132           // 128 floats + pad
#define SA_ELEMS (BM * AS_STRIDE)   // 4608 floats
#define SB_ELEMS (BK * BS_STRIDE)   // 4224 floats
#define SMEM_FLOATS (2 * SA_ELEMS + 2 * SB_ELEMS)   // 17664 floats = 70656 B

__device__ __forceinline__ void stage_tiles(
    uint32_t saA, uint32_t saB, const float* __restrict__ A,
    int mBase, int nBase, int k0, int tid)
{
    // A tile: 128 rows x 32 floats -> [m][k] row-major, stride 36
    #pragma unroll
    for (int p = 0; p < 4; ++p) {
        int c    = p * 256 + tid;         // 0..1023
        int row  = c >> 3;                // 0..127
        int c4   = c & 7;                 // float4 within row
        int grow = mBase + row;
        int ok   = (grow < N_NODES);
        const float* src = A + (size_t)(ok ? grow : 0) * DIM + k0 + c4 * 4;
        cp16(saA + (uint32_t)(row * AS_STRIDE + c4 * 4) * 4, src, ok ? 16u : 0u);
    }
    // B tile: 32 rows (k) x 128 floats (n) -> [k][n] row-major, stride 132
    #pragma unroll
    for (int p = 0; p < 4; ++p) {
        int c   = p * 256 + tid;          // 0..1023
        int row = c >> 5;                 // 0..31
        int c4  = c & 31;
        const float* src = g_Wr + (size_t)(k0 + row) * DIM + nBase + c4 * 4;
        cp16(saB + (uint32_t)(row * BS_STRIDE + c4 * 4) * 4, src, 16u);
    }
}

__global__ __launch_bounds__(256, 2) void mma_gemm_kernel(
    const float* __restrict__ A,     // g_agg [M, K] tf32-rounded
    const float* __restrict__ bias,  // [N]
    const float* __restrict__ X,     // [M, N]
    float* __restrict__ out)         // [M, N]
{
    extern __shared__ float sm[];
    const uint32_t sb = smem_u32(sm);
    const uint32_t SA[2] = { sb, sb + SA_ELEMS * 4 };
    const uint32_t SB[2] = { sb + 2 * SA_ELEMS * 4, sb + 2 * SA_ELEMS * 4 + SB_ELEMS * 4 };

    const int tid  = threadIdx.x;
    const int wid  = tid >> 5;
    const int lane = tid & 31;
    const int gid  = lane >> 2;       // group id (0..7)
    const int tig  = lane & 3;        // thread in group (0..3)
    const int wm   = wid & 3;         // warp row (0..3) -> 32 rows each
    const int wn   = wid >> 2;        // warp col (0..1) -> 64 cols each

    const int mBase = blockIdx.y * BM;
    const int nBase = blockIdx.x * BN;

    float acc[2][8][4];
    #pragma unroll
    for (int i = 0; i < 2; ++i)
        #pragma unroll
        for (int j = 0; j < 8; ++j)
            #pragma unroll
            for (int q = 0; q < 4; ++q) acc[i][j][q] = 0.f;

    stage_tiles(SA[0], SB[0], A, mBase, nBase, 0, tid);
    CP_COMMIT();

    int buf = 0;
    for (int it = 0; it < NKI; ++it) {
        if (it + 1 < NKI) {
            stage_tiles(SA[buf ^ 1], SB[buf ^ 1], A, mBase, nBase, (it + 1) * BK, tid);
            CP_COMMIT();
            CP_WAIT_1();
        } else {
            CP_WAIT_0();
        }
        __syncthreads();

        const uint32_t* AsU = reinterpret_cast<const uint32_t*>(sm) + buf * SA_ELEMS;
        const uint32_t* BsU = reinterpret_cast<const uint32_t*>(sm) + 2 * SA_ELEMS + buf * SB_ELEMS;

        #pragma unroll
        for (int ks = 0; ks < 4; ++ks) {
            const int kk = ks * 8;
            uint32_t a[2][4];
            #pragma unroll
            for (int i = 0; i < 2; ++i) {
                int r0 = wm * 32 + i * 16 + gid;
                a[i][0] = AsU[(r0    ) * AS_STRIDE + kk + tig    ];
                a[i][1] = AsU[(r0 + 8) * AS_STRIDE + kk + tig    ];
                a[i][2] = AsU[(r0    ) * AS_STRIDE + kk + tig + 4];
                a[i][3] = AsU[(r0 + 8) * AS_STRIDE + kk + tig + 4];
            }
            uint32_t b[8][2];
            #pragma unroll
            for (int j = 0; j < 8; ++j) {
                int n0 = wn * 64 + j * 8 + gid;
                b[j][0] = BsU[(kk + tig    ) * BS_STRIDE + n0];
                b[j][1] = BsU[(kk + tig + 4) * BS_STRIDE + n0];
            }
            #pragma unroll
            for (int i = 0; i < 2; ++i)
                #pragma unroll
                for (int j = 0; j < 8; ++j)
                    mma_tf32(acc[i][j], a[i], b[j]);
        }
        __syncthreads();
        buf ^= 1;
    }

    // epilogue: out = relu(acc + bias) + X
    #pragma unroll
    for (int i = 0; i < 2; ++i) {
        int r0 = mBase + wm * 32 + i * 16 + gid;
        int r1 = r0 + 8;
        #pragma unroll
        for (int j = 0; j < 8; ++j) {
            int col = nBase + wn * 64 + j * 8 + tig * 2;
            float2 bb = *reinterpret_cast<const float2*>(&bias[col]);
            if (r0 < N_NODES) {
                float2 xr = *reinterpret_cast<const float2*>(&X[(size_t)r0 * DIM + col]);
                float2 o;
                o.x = fmaxf(acc[i][j][0] + bb.x, 0.f) + xr.x;
                o.y = fmaxf(acc[i][j][1] + bb.y, 0.f) + xr.y;
                *reinterpret_cast<float2*>(&out[(size_t)r0 * DIM + col]) = o;
            }
            if (r1 < N_NODES) {
                float2 xr = *reinterpret_cast<const float2*>(&X[(size_t)r1 * DIM + col]);
                float2 o;
                o.x = fmaxf(acc[i][j][2] + bb.x, 0.f) + xr.x;
                o.y = fmaxf(acc[i][j][3] + bb.y, 0.f) + xr.y;
                *reinterpret_cast<float2*>(&out[(size_t)r1 * DIM + col]) = o;
            }
        }
    }
}

// ---------------- launch ----------------
extern "C" void kernel_launch(void* const* d_in, const int* in_sizes, int n_in,
                              void* d_out, int out_size) {
    const float* x    = (const float*)d_in[0];  // [N, D]
    const float* W    = (const float*)d_in[1];  // [D, D]
    const float* b    = (const float*)d_in[2];  // [D]
    const float* ew   = (const float*)d_in[3];  // [E]
    const int*   esrc = (const int*)  d_in[4];  // [E]
    const int*   edst = (const int*)  d_in[5];  // [E]
    float* out = (float*)d_out;

    float* agg_ptr;
    cudaGetSymbolAddress((void**)&agg_ptr, g_agg);

    // unconditional (no static guards) — host-side attribute set, capture-safe
    cudaFuncSetAttribute(mma_gemm_kernel,
                         cudaFuncAttributeMaxDynamicSharedMemorySize,
                         SMEM_FLOATS * 4);

    zero_offsets_kernel<<<(N_NODES + 256) / 256, 256>>>();
    hist_kernel<<<N_EDGES / 256, 256>>>(edst);
    round_w_kernel<<<(DIM * DIM / 4) / 256, 256>>>(reinterpret_cast<const float4*>(W));
    scan_kernel<<<1, 1024>>>();
    fill_kernel<<<N_EDGES / 256, 256>>>(esrc, edst, ew);
    aggregate_kernel<<<N_NODES, 128>>>(reinterpret_cast<const float4*>(x));

    dim3 ggrid(DIM / BN, (N_NODES + BM - 1) / BM);
    mma_gemm_kernel<<<ggrid, 256, SMEM_FLOATS * 4>>>(agg_ptr, b, x, out);
}